// round 9
// baseline (speedup 1.0000x reference)
#include <cuda_runtime.h>
#include <cuda_bf16.h>
#include <cstdint>

#define N_NODES 1000000
#define N_EDGES 8000000
#define NEG_SLOPE 0.01f
#define EPS_F 1e-10f
#define SCAN_NB ((N_NODES + 1023) / 1024)   // 977

#define DEPTH 3
#define SLOT_STRIDE (DEPTH * 256 + 16)      // 784 B: stagger slots across banks

// ---------------- static device scratch (no allocation allowed) --------------
__device__ float g_h[(size_t)N_NODES * 64];   // projected h: [node][64], ch0 cols 0-31, ch1 cols 32-63
__device__ int   g_cnt[N_NODES];              // edge count per destination row
__device__ int   g_off[N_NODES + 1];          // CSR offsets (exclusive scan of cnt)
__device__ int   g_cur[N_NODES];              // write cursors (init = off)
__device__ int   g_scol[N_EDGES];             // edge src (col) sorted by destination row
__device__ int   g_bsum[1024];                // scan block sums

// ---------------- helpers ----------------------------------------------------
__device__ __forceinline__ float leaky(float v) { return v > 0.f ? v : NEG_SLOPE * v; }

__device__ __forceinline__ void fma_f32x2(unsigned long long& d,
                                          unsigned long long a,
                                          unsigned long long b) {
    asm("fma.rn.f32x2 %0, %1, %2, %0;" : "+l"(d) : "l"(a), "l"(b));
}
__device__ __forceinline__ unsigned long long pack2(float x, float y) {
    unsigned long long r;
    asm("mov.b64 %0, {%1, %2};" : "=l"(r) : "f"(x), "f"(y));
    return r;
}
__device__ __forceinline__ float2 unpack2(unsigned long long v) {
    float2 r;
    asm("mov.b64 {%0, %1}, %2;" : "=f"(r.x), "=f"(r.y) : "l"(v));
    return r;
}

__device__ __forceinline__ void cp_async16(uint32_t smem_dst, const void* gsrc) {
    asm volatile("cp.async.cg.shared.global [%0], [%1], 16;"
                 :: "r"(smem_dst), "l"(gsrc) : "memory");
}
__device__ __forceinline__ void cp_commit() {
    asm volatile("cp.async.commit_group;" ::: "memory");
}
template <int N>
__device__ __forceinline__ void cp_wait() {
    asm volatile("cp.async.wait_group %0;" :: "n"(N) : "memory");
}

__device__ __forceinline__ int warp_incl_scan(int v) {
    #pragma unroll
    for (int s = 1; s < 32; s <<= 1) {
        int n = __shfl_up_sync(0xffffffffu, v, s);
        if ((threadIdx.x & 31) >= s) v += n;
    }
    return v;
}

// ---------------- kernel 0: zero counters ------------------------------------
__global__ void zero_kernel() {
    int i = blockIdx.x * blockDim.x + threadIdx.x;
    int stride = gridDim.x * blockDim.x;
    int4* c4 = (int4*)g_cnt;
    int4 z = make_int4(0, 0, 0, 0);
    for (int j = i; j < N_NODES / 4; j += stride) c4[j] = z;
    if (i == 0) g_off[N_NODES] = N_EDGES;
}

// ---------------- kernel 1: projection  h = leaky(ego @ W + b) ---------------
__global__ void project_kernel(const float* __restrict__ ego,
                               const float* __restrict__ W,
                               const float* __restrict__ b) {
    __shared__ unsigned long long Ws2[64 * 32];   // (W0[k][j], W1[k][j])
    __shared__ unsigned long long Bs2[32];
    int t = threadIdx.x;
    for (int idx = t; idx < 64 * 32; idx += blockDim.x) {
        int k = idx >> 5, j = idx & 31;
        Ws2[idx] = pack2(W[k * 32 + j], W[2048 + k * 32 + j]);
    }
    if (t < 32) Bs2[t] = pack2(b[t], b[32 + t]);
    __syncthreads();

    int lane = t & 31;
    int warp = (blockIdx.x * blockDim.x + t) >> 5;
    int nwarps = (gridDim.x * blockDim.x) >> 5;
    for (int base = warp * 4; base < N_NODES; base += nwarps * 4) {
        float2 e0 = *(const float2*)(ego + (size_t)(base + 0) * 64 + 2 * lane);
        float2 e1 = *(const float2*)(ego + (size_t)(base + 1) * 64 + 2 * lane);
        float2 e2 = *(const float2*)(ego + (size_t)(base + 2) * 64 + 2 * lane);
        float2 e3 = *(const float2*)(ego + (size_t)(base + 3) * 64 + 2 * lane);
        unsigned long long a0 = Bs2[lane], a1 = a0, a2 = a0, a3 = a0;
        #pragma unroll
        for (int k = 0; k < 64; k++) {
            unsigned long long wv = Ws2[k * 32 + lane];
            float s0 = __shfl_sync(0xffffffffu, (k & 1) ? e0.y : e0.x, k >> 1);
            float s1 = __shfl_sync(0xffffffffu, (k & 1) ? e1.y : e1.x, k >> 1);
            float s2 = __shfl_sync(0xffffffffu, (k & 1) ? e2.y : e2.x, k >> 1);
            float s3 = __shfl_sync(0xffffffffu, (k & 1) ? e3.y : e3.x, k >> 1);
            fma_f32x2(a0, pack2(s0, s0), wv);
            fma_f32x2(a1, pack2(s1, s1), wv);
            fma_f32x2(a2, pack2(s2, s2), wv);
            fma_f32x2(a3, pack2(s3, s3), wv);
        }
        float2 r0 = unpack2(a0), r1 = unpack2(a1), r2 = unpack2(a2), r3 = unpack2(a3);
        g_h[(size_t)(base + 0) * 64 + lane]      = leaky(r0.x);
        g_h[(size_t)(base + 0) * 64 + 32 + lane] = leaky(r0.y);
        g_h[(size_t)(base + 1) * 64 + lane]      = leaky(r1.x);
        g_h[(size_t)(base + 1) * 64 + 32 + lane] = leaky(r1.y);
        g_h[(size_t)(base + 2) * 64 + lane]      = leaky(r2.x);
        g_h[(size_t)(base + 2) * 64 + 32 + lane] = leaky(r2.y);
        g_h[(size_t)(base + 3) * 64 + lane]      = leaky(r3.x);
        g_h[(size_t)(base + 3) * 64 + 32 + lane] = leaky(r3.y);
    }
}

// ---------------- kernel 2: histogram of destination rows (int4 reads) -------
__global__ void hist_kernel(const int* __restrict__ row) {
    const int4* row4 = (const int4*)row;
    int i = blockIdx.x * blockDim.x + threadIdx.x;
    int stride = gridDim.x * blockDim.x;
    for (; i < N_EDGES / 4; i += stride) {
        int4 v = row4[i];
        atomicAdd(&g_cnt[v.x], 1);
        atomicAdd(&g_cnt[v.y], 1);
        atomicAdd(&g_cnt[v.z], 1);
        atomicAdd(&g_cnt[v.w], 1);
    }
}

// ---------------- kernels 3-5: exclusive scan of g_cnt -> g_off, g_cur -------
__global__ void scan1_kernel() {
    __shared__ int wsum[32];
    int t = threadIdx.x;
    int i = blockIdx.x * 1024 + t;
    int v = (i < N_NODES) ? g_cnt[i] : 0;
    int incl = warp_incl_scan(v);
    int wid = t >> 5, lid = t & 31;
    if (lid == 31) wsum[wid] = incl;
    __syncthreads();
    if (wid == 0) {
        int w = wsum[lid];
        int ws = warp_incl_scan(w);
        wsum[lid] = ws - w;
    }
    __syncthreads();
    int excl = incl - v + wsum[wid];
    if (i < N_NODES) g_off[i] = excl;
    if (t == 1023) g_bsum[blockIdx.x] = excl + v;
}

__global__ void scan2_kernel() {
    __shared__ int wsum[32];
    int t = threadIdx.x;
    int v = (t < SCAN_NB) ? g_bsum[t] : 0;
    int incl = warp_incl_scan(v);
    int wid = t >> 5, lid = t & 31;
    if (lid == 31) wsum[wid] = incl;
    __syncthreads();
    if (wid == 0) {
        int w = wsum[lid];
        int ws = warp_incl_scan(w);
        wsum[lid] = ws - w;
    }
    __syncthreads();
    int excl = incl - v + wsum[wid];
    if (t < SCAN_NB) g_bsum[t] = excl;
}

__global__ void scan3_kernel() {
    int i = blockIdx.x * 1024 + threadIdx.x;
    if (i < N_NODES) {
        int off = g_off[i] + g_bsum[blockIdx.x];
        g_off[i] = off;
        g_cur[i] = off;
    }
}

// ---------------- kernel 6: permute (counting sort of col, int4 reads) -------
__global__ void permute_kernel(const int* __restrict__ row, const int* __restrict__ col) {
    const int4* row4 = (const int4*)row;
    const int4* col4 = (const int4*)col;
    int i = blockIdx.x * blockDim.x + threadIdx.x;
    int stride = gridDim.x * blockDim.x;
    for (; i < N_EDGES / 4; i += stride) {
        int4 r = row4[i];
        int4 c = col4[i];
        g_scol[atomicAdd(&g_cur[r.x], 1)] = c.x;
        g_scol[atomicAdd(&g_cur[r.y], 1)] = c.y;
        g_scol[atomicAdd(&g_cur[r.z], 1)] = c.z;
        g_scol[atomicAdd(&g_cur[r.w], 1)] = c.w;
    }
}

// ---------------- kernel 7: fused row pass with cp.async pipeline ------------
// One row per warp, 4 edge slots of 8 lanes, depth-3 cp.async smem ring per
// slot. Each lane consumes exactly the 2x16B it copied -> per-thread
// commit/wait ordering, NO barriers in the loop. Warp-uniform trip count
// (m = ceil(deg/4)); phantom edges predicated to ex=0.
//   out = sum(ex*h_col) / (sum_ex + EPS)
__global__ void __launch_bounds__(256) row_kernel(float* __restrict__ out) {
    __shared__ char buf[32 * SLOT_STRIDE];    // 8 warps * 4 slots * 784B = 25088B

    int t = threadIdx.x;
    int lane = t & 31;
    int w = t >> 5;
    int slot = lane >> 3;                     // 0..3
    int s = lane & 7;                         // 0..7
    int r = blockIdx.x * 8 + w;               // exactly one row per warp

    int start = g_off[r];
    int deg   = g_off[r + 1] - start;
    int m = (deg + 3) >> 2;                   // warp-uniform trip count

    const float4 hr0 = *(const float4*)(g_h + (size_t)r * 64 + 4 * s);
    const float4 hr1 = *(const float4*)(g_h + (size_t)r * 64 + 32 + 4 * s);

    uint32_t sb = (uint32_t)__cvta_generic_to_shared(buf + (w * 4 + slot) * SLOT_STRIDE)
                  + 16 * s;

    float se0 = 0.f, se1 = 0.f;
    float4 a0 = make_float4(0.f, 0.f, 0.f, 0.f);
    float4 a1 = make_float4(0.f, 0.f, 0.f, 0.f);

    int clampv = (deg > 0) ? deg - 1 : 0;

    // prologue: fill up to DEPTH stages
    #pragma unroll
    for (int j = 0; j < DEPTH; j++) {
        if (j < m) {
            int pos = slot + (j << 2);
            int c = g_scol[start + (pos < deg ? pos : clampv)];
            const float* src = g_h + (size_t)c * 64 + 4 * s;
            cp_async16(sb + j * 256, src);
            cp_async16(sb + j * 256 + 128, src + 32);
        }
        cp_commit();
    }

    int stage = 0;
    for (int k = 0; k < m; k++) {
        cp_wait<DEPTH - 1>();
        // consume stage (each lane reads its own copied bytes)
        float4 hc0 = *(float4*)(buf + (w * 4 + slot) * SLOT_STRIDE + stage * 256 + 16 * s);
        float4 hc1 = *(float4*)(buf + (w * 4 + slot) * SLOT_STRIDE + stage * 256 + 128 + 16 * s);

        // refill same stage with edge k+DEPTH
        int kp = k + DEPTH;
        if (kp < m) {
            int pos = slot + (kp << 2);
            int c = g_scol[start + (pos < deg ? pos : clampv)];
            const float* src = g_h + (size_t)c * 64 + 4 * s;
            cp_async16(sb + stage * 256, src);
            cp_async16(sb + stage * 256 + 128, src + 32);
        }
        cp_commit();

        bool valid = (slot + (k << 2)) < deg;
        float d0 = hr0.x * hc0.x + hr0.y * hc0.y + hr0.z * hc0.z + hr0.w * hc0.w;
        float d1 = hr1.x * hc1.x + hr1.y * hc1.y + hr1.z * hc1.z + hr1.w * hc1.w;
        d0 += __shfl_xor_sync(0xffffffffu, d0, 4);
        d1 += __shfl_xor_sync(0xffffffffu, d1, 4);
        d0 += __shfl_xor_sync(0xffffffffu, d0, 2);
        d1 += __shfl_xor_sync(0xffffffffu, d1, 2);
        d0 += __shfl_xor_sync(0xffffffffu, d0, 1);
        d1 += __shfl_xor_sync(0xffffffffu, d1, 1);
        float ex0 = valid ? __expf(leaky(d0)) : 0.f;
        float ex1 = valid ? __expf(leaky(d1)) : 0.f;
        se0 += ex0;
        se1 += ex1;
        a0.x += ex0 * hc0.x; a0.y += ex0 * hc0.y;
        a0.z += ex0 * hc0.z; a0.w += ex0 * hc0.w;
        a1.x += ex1 * hc1.x; a1.y += ex1 * hc1.y;
        a1.z += ex1 * hc1.z; a1.w += ex1 * hc1.w;

        stage = (stage == DEPTH - 1) ? 0 : stage + 1;
    }

    __syncwarp();
    // combine the 4 slot partials (xor 8, then xor 16)
    #pragma unroll
    for (int off = 8; off <= 16; off <<= 1) {
        se0 += __shfl_xor_sync(0xffffffffu, se0, off);
        se1 += __shfl_xor_sync(0xffffffffu, se1, off);
        a0.x += __shfl_xor_sync(0xffffffffu, a0.x, off);
        a0.y += __shfl_xor_sync(0xffffffffu, a0.y, off);
        a0.z += __shfl_xor_sync(0xffffffffu, a0.z, off);
        a0.w += __shfl_xor_sync(0xffffffffu, a0.w, off);
        a1.x += __shfl_xor_sync(0xffffffffu, a1.x, off);
        a1.y += __shfl_xor_sync(0xffffffffu, a1.y, off);
        a1.z += __shfl_xor_sync(0xffffffffu, a1.z, off);
        a1.w += __shfl_xor_sync(0xffffffffu, a1.w, off);
    }
    if (lane < 8) {
        float sc0 = 1.0f / (se0 + EPS_F);
        float sc1 = 1.0f / (se1 + EPS_F);
        *(float4*)(out + (size_t)r * 64 + 4 * s) =
            make_float4(a0.x * sc0, a0.y * sc0, a0.z * sc0, a0.w * sc0);
        *(float4*)(out + (size_t)r * 64 + 32 + 4 * s) =
            make_float4(a1.x * sc1, a1.y * sc1, a1.z * sc1, a1.w * sc1);
    }
}

// ---------------- launcher ---------------------------------------------------
extern "C" void kernel_launch(void* const* d_in, const int* in_sizes, int n_in,
                              void* d_out, int out_size) {
    const float* ego = (const float*)d_in[0];   // [1M, 64] f32
    const float* W   = (const float*)d_in[1];   // [2, 64, 32] f32
    const float* b   = (const float*)d_in[2];   // [2, 1, 32] f32
    const int* row   = (const int*)d_in[3];     // [8M] i32 (destination)
    const int* col   = (const int*)d_in[4];     // [8M] i32 (source)
    float* out       = (float*)d_out;           // [1M, 64] f32

    zero_kernel<<<1024, 256>>>();
    project_kernel<<<2048, 256>>>(ego, W, b);
    hist_kernel<<<4096, 256>>>(row);
    scan1_kernel<<<SCAN_NB, 1024>>>();
    scan2_kernel<<<1, 1024>>>();
    scan3_kernel<<<SCAN_NB, 1024>>>();
    permute_kernel<<<4096, 256>>>(row, col);
    row_kernel<<<125000, 256>>>(out);           // 8 rows per block, 1 warp each
}

// round 10
// speedup vs baseline: 1.0456x; 1.0456x over previous
#include <cuda_runtime.h>
#include <cuda_bf16.h>
#include <cstdint>

#define N_NODES 1000000
#define N_EDGES 8000000
#define NEG_SLOPE 0.01f
#define EPS_F 1e-10f
#define SCAN_NB ((N_NODES + 1023) / 1024)   // 977

// ---------------- static device scratch (no allocation allowed) --------------
__device__ float g_h[(size_t)N_NODES * 64];   // projected h: [node][64], ch0 cols 0-31, ch1 cols 32-63
__device__ int   g_cnt[N_NODES];              // edge count per destination row
__device__ int   g_off[N_NODES + 1];          // CSR offsets (exclusive scan of cnt)
__device__ int   g_cur[N_NODES];              // write cursors (init = off)
__device__ int   g_scol[N_EDGES];             // edge src (col) sorted by destination row
__device__ int   g_bsum[1024];                // scan block sums

// ---------------- helpers ----------------------------------------------------
__device__ __forceinline__ float leaky(float v) { return v > 0.f ? v : NEG_SLOPE * v; }

__device__ __forceinline__ void fma_f32x2(unsigned long long& d,
                                          unsigned long long a,
                                          unsigned long long b) {
    asm("fma.rn.f32x2 %0, %1, %2, %0;" : "+l"(d) : "l"(a), "l"(b));
}
__device__ __forceinline__ unsigned long long pack2(float x, float y) {
    unsigned long long r;
    asm("mov.b64 %0, {%1, %2};" : "=l"(r) : "f"(x), "f"(y));
    return r;
}
__device__ __forceinline__ float2 unpack2(unsigned long long v) {
    float2 r;
    asm("mov.b64 {%0, %1}, %2;" : "=f"(r.x), "=f"(r.y) : "l"(v));
    return r;
}

__device__ __forceinline__ int warp_incl_scan(int v) {
    #pragma unroll
    for (int s = 1; s < 32; s <<= 1) {
        int n = __shfl_up_sync(0xffffffffu, v, s);
        if ((threadIdx.x & 31) >= s) v += n;
    }
    return v;
}

// ---------------- kernel 0: zero counters ------------------------------------
__global__ void zero_kernel() {
    int i = blockIdx.x * blockDim.x + threadIdx.x;
    int stride = gridDim.x * blockDim.x;
    int4* c4 = (int4*)g_cnt;
    int4 z = make_int4(0, 0, 0, 0);
    for (int j = i; j < N_NODES / 4; j += stride) c4[j] = z;
    if (i == 0) g_off[N_NODES] = N_EDGES;
}

// ---------------- kernel 1: projection  h = leaky(ego @ W + b) ---------------
// 4 nodes per warp; lane j computes (ch0 col j, ch1 col j) packed as f32x2.
__global__ void project_kernel(const float* __restrict__ ego,
                               const float* __restrict__ W,
                               const float* __restrict__ b) {
    __shared__ unsigned long long Ws2[64 * 32];   // (W0[k][j], W1[k][j])
    __shared__ unsigned long long Bs2[32];
    int t = threadIdx.x;
    for (int idx = t; idx < 64 * 32; idx += blockDim.x) {
        int k = idx >> 5, j = idx & 31;
        Ws2[idx] = pack2(W[k * 32 + j], W[2048 + k * 32 + j]);
    }
    if (t < 32) Bs2[t] = pack2(b[t], b[32 + t]);
    __syncthreads();

    int lane = t & 31;
    int warp = (blockIdx.x * blockDim.x + t) >> 5;
    int nwarps = (gridDim.x * blockDim.x) >> 5;
    for (int base = warp * 4; base < N_NODES; base += nwarps * 4) {
        float2 e0 = *(const float2*)(ego + (size_t)(base + 0) * 64 + 2 * lane);
        float2 e1 = *(const float2*)(ego + (size_t)(base + 1) * 64 + 2 * lane);
        float2 e2 = *(const float2*)(ego + (size_t)(base + 2) * 64 + 2 * lane);
        float2 e3 = *(const float2*)(ego + (size_t)(base + 3) * 64 + 2 * lane);
        unsigned long long a0 = Bs2[lane], a1 = a0, a2 = a0, a3 = a0;
        #pragma unroll
        for (int k = 0; k < 64; k++) {
            unsigned long long wv = Ws2[k * 32 + lane];
            float s0 = __shfl_sync(0xffffffffu, (k & 1) ? e0.y : e0.x, k >> 1);
            float s1 = __shfl_sync(0xffffffffu, (k & 1) ? e1.y : e1.x, k >> 1);
            float s2 = __shfl_sync(0xffffffffu, (k & 1) ? e2.y : e2.x, k >> 1);
            float s3 = __shfl_sync(0xffffffffu, (k & 1) ? e3.y : e3.x, k >> 1);
            fma_f32x2(a0, pack2(s0, s0), wv);
            fma_f32x2(a1, pack2(s1, s1), wv);
            fma_f32x2(a2, pack2(s2, s2), wv);
            fma_f32x2(a3, pack2(s3, s3), wv);
        }
        float2 r0 = unpack2(a0), r1 = unpack2(a1), r2 = unpack2(a2), r3 = unpack2(a3);
        g_h[(size_t)(base + 0) * 64 + lane]      = leaky(r0.x);
        g_h[(size_t)(base + 0) * 64 + 32 + lane] = leaky(r0.y);
        g_h[(size_t)(base + 1) * 64 + lane]      = leaky(r1.x);
        g_h[(size_t)(base + 1) * 64 + 32 + lane] = leaky(r1.y);
        g_h[(size_t)(base + 2) * 64 + lane]      = leaky(r2.x);
        g_h[(size_t)(base + 2) * 64 + 32 + lane] = leaky(r2.y);
        g_h[(size_t)(base + 3) * 64 + lane]      = leaky(r3.x);
        g_h[(size_t)(base + 3) * 64 + 32 + lane] = leaky(r3.y);
    }
}

// ---------------- kernel 2: histogram of destination rows (int4 reads) -------
__global__ void hist_kernel(const int* __restrict__ row) {
    const int4* row4 = (const int4*)row;
    int i = blockIdx.x * blockDim.x + threadIdx.x;
    int stride = gridDim.x * blockDim.x;
    for (; i < N_EDGES / 4; i += stride) {
        int4 v = row4[i];
        atomicAdd(&g_cnt[v.x], 1);
        atomicAdd(&g_cnt[v.y], 1);
        atomicAdd(&g_cnt[v.z], 1);
        atomicAdd(&g_cnt[v.w], 1);
    }
}

// ---------------- kernels 3-5: exclusive scan of g_cnt -> g_off, g_cur -------
__global__ void scan1_kernel() {
    __shared__ int wsum[32];
    int t = threadIdx.x;
    int i = blockIdx.x * 1024 + t;
    int v = (i < N_NODES) ? g_cnt[i] : 0;
    int incl = warp_incl_scan(v);
    int wid = t >> 5, lid = t & 31;
    if (lid == 31) wsum[wid] = incl;
    __syncthreads();
    if (wid == 0) {
        int w = wsum[lid];
        int ws = warp_incl_scan(w);
        wsum[lid] = ws - w;
    }
    __syncthreads();
    int excl = incl - v + wsum[wid];
    if (i < N_NODES) g_off[i] = excl;
    if (t == 1023) g_bsum[blockIdx.x] = excl + v;
}

__global__ void scan2_kernel() {
    __shared__ int wsum[32];
    int t = threadIdx.x;
    int v = (t < SCAN_NB) ? g_bsum[t] : 0;
    int incl = warp_incl_scan(v);
    int wid = t >> 5, lid = t & 31;
    if (lid == 31) wsum[wid] = incl;
    __syncthreads();
    if (wid == 0) {
        int w = wsum[lid];
        int ws = warp_incl_scan(w);
        wsum[lid] = ws - w;
    }
    __syncthreads();
    int excl = incl - v + wsum[wid];
    if (t < SCAN_NB) g_bsum[t] = excl;
}

__global__ void scan3_kernel() {
    int i = blockIdx.x * 1024 + threadIdx.x;
    if (i < N_NODES) {
        int off = g_off[i] + g_bsum[blockIdx.x];
        g_off[i] = off;
        g_cur[i] = off;
    }
}

// ---------------- kernel 6: permute (counting sort of col, int4 reads) -------
__global__ void permute_kernel(const int* __restrict__ row, const int* __restrict__ col) {
    const int4* row4 = (const int4*)row;
    const int4* col4 = (const int4*)col;
    int i = blockIdx.x * blockDim.x + threadIdx.x;
    int stride = gridDim.x * blockDim.x;
    for (; i < N_EDGES / 4; i += stride) {
        int4 r = row4[i];
        int4 c = col4[i];
        g_scol[atomicAdd(&g_cur[r.x], 1)] = c.x;
        g_scol[atomicAdd(&g_cur[r.y], 1)] = c.y;
        g_scol[atomicAdd(&g_cur[r.z], 1)] = c.z;
        g_scol[atomicAdd(&g_cur[r.w], 1)] = c.w;
    }
}

// ---------------- kernel 7: fused logits + softmax + aggregation -------------
// ONE row per warp, FOUR edge slots of 8 lanes each (register prefetch, depth 2).
// This is the proven round-8 version (cp.async variant regressed: rows are too
// short for deep intra-row pipelines; per-row setup chain dominates).
//   out = sum(ex*h_col) / (sum_ex + EPS)
__global__ void row_kernel(float* __restrict__ out) {
    int t = blockIdx.x * blockDim.x + threadIdx.x;
    int lane = t & 31;
    int slot = lane >> 3;                     // 0..3: edge slot
    int s = lane & 7;                         // lane within slot
    unsigned smask = 0xFFu << (slot * 8);     // slot's 8-lane shuffle mask
    int warp = t >> 5;                        // exactly one row per warp
    if (warp >= N_NODES) return;
    int r = warp;

    int start = g_off[r];
    int end   = g_off[r + 1];
    const float4 hr0 = *(const float4*)(g_h + (size_t)r * 64 + 4 * s);
    const float4 hr1 = *(const float4*)(g_h + (size_t)r * 64 + 32 + 4 * s);

    float se0 = 0.f, se1 = 0.f;
    float4 a0 = make_float4(0.f, 0.f, 0.f, 0.f);
    float4 a1 = make_float4(0.f, 0.f, 0.f, 0.f);

    int i = start + slot;
    if (i < end) {
        int c = g_scol[i];
        float4 hc0 = *(const float4*)(g_h + (size_t)c * 64 + 4 * s);
        float4 hc1 = *(const float4*)(g_h + (size_t)c * 64 + 32 + 4 * s);
        while (true) {
            int inext = i + 4;
            bool more = inext < end;
            float4 hn0, hn1;
            if (more) {
                int cn = g_scol[inext];
                hn0 = *(const float4*)(g_h + (size_t)cn * 64 + 4 * s);
                hn1 = *(const float4*)(g_h + (size_t)cn * 64 + 32 + 4 * s);
            }
            float d0 = hr0.x * hc0.x + hr0.y * hc0.y + hr0.z * hc0.z + hr0.w * hc0.w;
            float d1 = hr1.x * hc1.x + hr1.y * hc1.y + hr1.z * hc1.z + hr1.w * hc1.w;
            d0 += __shfl_xor_sync(smask, d0, 4);
            d1 += __shfl_xor_sync(smask, d1, 4);
            d0 += __shfl_xor_sync(smask, d0, 2);
            d1 += __shfl_xor_sync(smask, d1, 2);
            d0 += __shfl_xor_sync(smask, d0, 1);
            d1 += __shfl_xor_sync(smask, d1, 1);
            float ex0 = __expf(leaky(d0));
            float ex1 = __expf(leaky(d1));
            se0 += ex0;
            se1 += ex1;
            a0.x += ex0 * hc0.x; a0.y += ex0 * hc0.y;
            a0.z += ex0 * hc0.z; a0.w += ex0 * hc0.w;
            a1.x += ex1 * hc1.x; a1.y += ex1 * hc1.y;
            a1.z += ex1 * hc1.z; a1.w += ex1 * hc1.w;
            if (!more) break;
            hc0 = hn0; hc1 = hn1; i = inext;
        }
    }
    __syncwarp();
    // combine the 4 slot partials (xor 8, then xor 16)
    #pragma unroll
    for (int off = 8; off <= 16; off <<= 1) {
        se0 += __shfl_xor_sync(0xffffffffu, se0, off);
        se1 += __shfl_xor_sync(0xffffffffu, se1, off);
        a0.x += __shfl_xor_sync(0xffffffffu, a0.x, off);
        a0.y += __shfl_xor_sync(0xffffffffu, a0.y, off);
        a0.z += __shfl_xor_sync(0xffffffffu, a0.z, off);
        a0.w += __shfl_xor_sync(0xffffffffu, a0.w, off);
        a1.x += __shfl_xor_sync(0xffffffffu, a1.x, off);
        a1.y += __shfl_xor_sync(0xffffffffu, a1.y, off);
        a1.z += __shfl_xor_sync(0xffffffffu, a1.z, off);
        a1.w += __shfl_xor_sync(0xffffffffu, a1.w, off);
    }
    if (lane < 8) {
        float sc0 = 1.0f / (se0 + EPS_F);
        float sc1 = 1.0f / (se1 + EPS_F);
        *(float4*)(out + (size_t)r * 64 + 4 * s) =
            make_float4(a0.x * sc0, a0.y * sc0, a0.z * sc0, a0.w * sc0);
        *(float4*)(out + (size_t)r * 64 + 32 + 4 * s) =
            make_float4(a1.x * sc1, a1.y * sc1, a1.z * sc1, a1.w * sc1);
    }
}

// ---------------- launcher ---------------------------------------------------
// Two-stream fork: project_kernel (FMA-bound) is independent of the
// zero->hist->scan->permute chain (atomic/memory-bound); they join before
// row_kernel. Fork/join via events is the standard capturable pattern and
// produces a forked graph. Stream/events are host-side plumbing created once
// (no device memory involved); the launched work is identical on every call.
static cudaStream_t g_s2 = nullptr;
static cudaEvent_t  g_ev_fork = nullptr;
static cudaEvent_t  g_ev_join = nullptr;

extern "C" void kernel_launch(void* const* d_in, const int* in_sizes, int n_in,
                              void* d_out, int out_size) {
    const float* ego = (const float*)d_in[0];   // [1M, 64] f32
    const float* W   = (const float*)d_in[1];   // [2, 64, 32] f32
    const float* b   = (const float*)d_in[2];   // [2, 1, 32] f32
    const int* row   = (const int*)d_in[3];     // [8M] i32 (destination)
    const int* col   = (const int*)d_in[4];     // [8M] i32 (source)
    float* out       = (float*)d_out;           // [1M, 64] f32

    if (g_s2 == nullptr) {
        cudaStreamCreateWithFlags(&g_s2, cudaStreamNonBlocking);
        cudaEventCreateWithFlags(&g_ev_fork, cudaEventDisableTiming);
        cudaEventCreateWithFlags(&g_ev_join, cudaEventDisableTiming);
    }

    // fork: side stream runs the projection concurrently
    cudaEventRecord(g_ev_fork, 0);
    cudaStreamWaitEvent(g_s2, g_ev_fork, 0);
    project_kernel<<<2048, 256, 0, g_s2>>>(ego, W, b);
    cudaEventRecord(g_ev_join, g_s2);

    // main stream: build sorted-edge structure
    zero_kernel<<<1024, 256>>>();
    hist_kernel<<<4096, 256>>>(row);
    scan1_kernel<<<SCAN_NB, 1024>>>();
    scan2_kernel<<<1, 1024>>>();
    scan3_kernel<<<SCAN_NB, 1024>>>();
    permute_kernel<<<4096, 256>>>(row, col);

    // join: row pass needs both g_h (projection) and g_scol/g_off (sort)
    cudaStreamWaitEvent(0, g_ev_join, 0);
    row_kernel<<<125000, 256>>>(out);           // exactly 1 warp per row
}

// round 11
// speedup vs baseline: 1.1802x; 1.1287x over previous
#include <cuda_runtime.h>
#include <cuda_bf16.h>
#include <cstdint>

#define N_NODES 1000000
#define N_EDGES 8000000
#define NEG_SLOPE 0.01f
#define EPS_F 1e-10f
#define SCAN_NB ((N_NODES + 1023) / 1024)   // 977

// ---------------- static device scratch (no allocation allowed) --------------
__device__ float g_h[(size_t)N_NODES * 64];   // projected h: [node][64], ch0 cols 0-31, ch1 cols 32-63
__device__ int   g_cnt[N_NODES];              // edge count per destination row
__device__ int   g_off[N_NODES + 1];          // CSR offsets (exclusive scan of cnt)
__device__ int   g_cur[N_NODES];              // write cursors (init = off)
__device__ int   g_scol[N_EDGES];             // edge src (col) sorted by destination row
__device__ int   g_bsum[1024];                // scan block sums

// ---------------- helpers ----------------------------------------------------
__device__ __forceinline__ float leaky(float v) { return v > 0.f ? v : NEG_SLOPE * v; }

__device__ __forceinline__ void fma_f32x2(unsigned long long& d,
                                          unsigned long long a,
                                          unsigned long long b) {
    asm("fma.rn.f32x2 %0, %1, %2, %0;" : "+l"(d) : "l"(a), "l"(b));
}
__device__ __forceinline__ unsigned long long pack2(float x, float y) {
    unsigned long long r;
    asm("mov.b64 %0, {%1, %2};" : "=l"(r) : "f"(x), "f"(y));
    return r;
}
__device__ __forceinline__ float2 unpack2(unsigned long long v) {
    float2 r;
    asm("mov.b64 {%0, %1}, %2;" : "=f"(r.x), "=f"(r.y) : "l"(v));
    return r;
}

__device__ __forceinline__ int warp_incl_scan(int v) {
    #pragma unroll
    for (int s = 1; s < 32; s <<= 1) {
        int n = __shfl_up_sync(0xffffffffu, v, s);
        if ((threadIdx.x & 31) >= s) v += n;
    }
    return v;
}

// ---------------- kernel 0: zero counters ------------------------------------
__global__ void zero_kernel() {
    int i = blockIdx.x * blockDim.x + threadIdx.x;
    int stride = gridDim.x * blockDim.x;
    int4* c4 = (int4*)g_cnt;
    int4 z = make_int4(0, 0, 0, 0);
    for (int j = i; j < N_NODES / 4; j += stride) c4[j] = z;
    if (i == 0) g_off[N_NODES] = N_EDGES;
}

// ---------------- kernel 1: projection  h = leaky(ego @ W + b) ---------------
__global__ void project_kernel(const float* __restrict__ ego,
                               const float* __restrict__ W,
                               const float* __restrict__ b) {
    __shared__ unsigned long long Ws2[64 * 32];   // (W0[k][j], W1[k][j])
    __shared__ unsigned long long Bs2[32];
    int t = threadIdx.x;
    for (int idx = t; idx < 64 * 32; idx += blockDim.x) {
        int k = idx >> 5, j = idx & 31;
        Ws2[idx] = pack2(W[k * 32 + j], W[2048 + k * 32 + j]);
    }
    if (t < 32) Bs2[t] = pack2(b[t], b[32 + t]);
    __syncthreads();

    int lane = t & 31;
    int warp = (blockIdx.x * blockDim.x + t) >> 5;
    int nwarps = (gridDim.x * blockDim.x) >> 5;
    for (int base = warp * 4; base < N_NODES; base += nwarps * 4) {
        float2 e0 = *(const float2*)(ego + (size_t)(base + 0) * 64 + 2 * lane);
        float2 e1 = *(const float2*)(ego + (size_t)(base + 1) * 64 + 2 * lane);
        float2 e2 = *(const float2*)(ego + (size_t)(base + 2) * 64 + 2 * lane);
        float2 e3 = *(const float2*)(ego + (size_t)(base + 3) * 64 + 2 * lane);
        unsigned long long a0 = Bs2[lane], a1 = a0, a2 = a0, a3 = a0;
        #pragma unroll
        for (int k = 0; k < 64; k++) {
            unsigned long long wv = Ws2[k * 32 + lane];
            float s0 = __shfl_sync(0xffffffffu, (k & 1) ? e0.y : e0.x, k >> 1);
            float s1 = __shfl_sync(0xffffffffu, (k & 1) ? e1.y : e1.x, k >> 1);
            float s2 = __shfl_sync(0xffffffffu, (k & 1) ? e2.y : e2.x, k >> 1);
            float s3 = __shfl_sync(0xffffffffu, (k & 1) ? e3.y : e3.x, k >> 1);
            fma_f32x2(a0, pack2(s0, s0), wv);
            fma_f32x2(a1, pack2(s1, s1), wv);
            fma_f32x2(a2, pack2(s2, s2), wv);
            fma_f32x2(a3, pack2(s3, s3), wv);
        }
        float2 r0 = unpack2(a0), r1 = unpack2(a1), r2 = unpack2(a2), r3 = unpack2(a3);
        g_h[(size_t)(base + 0) * 64 + lane]      = leaky(r0.x);
        g_h[(size_t)(base + 0) * 64 + 32 + lane] = leaky(r0.y);
        g_h[(size_t)(base + 1) * 64 + lane]      = leaky(r1.x);
        g_h[(size_t)(base + 1) * 64 + 32 + lane] = leaky(r1.y);
        g_h[(size_t)(base + 2) * 64 + lane]      = leaky(r2.x);
        g_h[(size_t)(base + 2) * 64 + 32 + lane] = leaky(r2.y);
        g_h[(size_t)(base + 3) * 64 + lane]      = leaky(r3.x);
        g_h[(size_t)(base + 3) * 64 + 32 + lane] = leaky(r3.y);
    }
}

// ---------------- kernel 2: histogram of destination rows (int4 reads) -------
__global__ void hist_kernel(const int* __restrict__ row) {
    const int4* row4 = (const int4*)row;
    int i = blockIdx.x * blockDim.x + threadIdx.x;
    int stride = gridDim.x * blockDim.x;
    for (; i < N_EDGES / 4; i += stride) {
        int4 v = row4[i];
        atomicAdd(&g_cnt[v.x], 1);
        atomicAdd(&g_cnt[v.y], 1);
        atomicAdd(&g_cnt[v.z], 1);
        atomicAdd(&g_cnt[v.w], 1);
    }
}

// ---------------- kernels 3-5: exclusive scan of g_cnt -> g_off, g_cur -------
__global__ void scan1_kernel() {
    __shared__ int wsum[32];
    int t = threadIdx.x;
    int i = blockIdx.x * 1024 + t;
    int v = (i < N_NODES) ? g_cnt[i] : 0;
    int incl = warp_incl_scan(v);
    int wid = t >> 5, lid = t & 31;
    if (lid == 31) wsum[wid] = incl;
    __syncthreads();
    if (wid == 0) {
        int w = wsum[lid];
        int ws = warp_incl_scan(w);
        wsum[lid] = ws - w;
    }
    __syncthreads();
    int excl = incl - v + wsum[wid];
    if (i < N_NODES) g_off[i] = excl;
    if (t == 1023) g_bsum[blockIdx.x] = excl + v;
}

__global__ void scan2_kernel() {
    __shared__ int wsum[32];
    int t = threadIdx.x;
    int v = (t < SCAN_NB) ? g_bsum[t] : 0;
    int incl = warp_incl_scan(v);
    int wid = t >> 5, lid = t & 31;
    if (lid == 31) wsum[wid] = incl;
    __syncthreads();
    if (wid == 0) {
        int w = wsum[lid];
        int ws = warp_incl_scan(w);
        wsum[lid] = ws - w;
    }
    __syncthreads();
    int excl = incl - v + wsum[wid];
    if (t < SCAN_NB) g_bsum[t] = excl;
}

__global__ void scan3_kernel() {
    int i = blockIdx.x * 1024 + threadIdx.x;
    if (i < N_NODES) {
        int off = g_off[i] + g_bsum[blockIdx.x];
        g_off[i] = off;
        g_cur[i] = off;
    }
}

// ---------------- kernel 6: permute (counting sort of col, int4 reads) -------
__global__ void permute_kernel(const int* __restrict__ row, const int* __restrict__ col) {
    const int4* row4 = (const int4*)row;
    const int4* col4 = (const int4*)col;
    int i = blockIdx.x * blockDim.x + threadIdx.x;
    int stride = gridDim.x * blockDim.x;
    for (; i < N_EDGES / 4; i += stride) {
        int4 r = row4[i];
        int4 c = col4[i];
        g_scol[atomicAdd(&g_cur[r.x], 1)] = c.x;
        g_scol[atomicAdd(&g_cur[r.y], 1)] = c.y;
        g_scol[atomicAdd(&g_cur[r.z], 1)] = c.z;
        g_scol[atomicAdd(&g_cur[r.w], 1)] = c.w;
    }
}

// ---------------- kernel 7: fused logits + softmax + aggregation -------------
// FOUR rows per warp: one 8-lane group per row. All 4 rows' setup loads
// (offsets, hr, first edge) are issued concurrently (4x setup MLP), and each
// group writes its own row at the end (no cross-slot combine tail).
// Warp-uniform trip count m = max(deg of 4 rows); exhausted groups are
// predicated (ex=0, clamped indices). Depth-2 register prefetch on gathers.
//   out = sum(ex*h_col) / (sum_ex + EPS)
__global__ void row_kernel(float* __restrict__ out) {
    int t = blockIdx.x * blockDim.x + threadIdx.x;
    int lane = t & 31;
    int g = lane >> 3;                        // 0..3: row group
    int s = lane & 7;                         // lane within group
    int warp = t >> 5;
    int r = warp * 4 + g;                     // this group's row (always < N_NODES)

    int start = g_off[r];
    int deg   = g_off[r + 1] - start;
    // warp-uniform trip count: max degree over the 4 groups
    int m = deg;
    m = max(m, __shfl_xor_sync(0xffffffffu, m, 8));
    m = max(m, __shfl_xor_sync(0xffffffffu, m, 16));

    const float4 hr0 = *(const float4*)(g_h + (size_t)r * 64 + 4 * s);
    const float4 hr1 = *(const float4*)(g_h + (size_t)r * 64 + 32 + 4 * s);

    float se0 = 0.f, se1 = 0.f;
    float4 a0 = make_float4(0.f, 0.f, 0.f, 0.f);
    float4 a1 = make_float4(0.f, 0.f, 0.f, 0.f);

    if (m > 0) {
        int clampv = (deg > 0) ? deg - 1 : 0;
        int c = g_scol[start + ((0 < deg) ? 0 : clampv)];
        float4 hc0 = *(const float4*)(g_h + (size_t)c * 64 + 4 * s);
        float4 hc1 = *(const float4*)(g_h + (size_t)c * 64 + 32 + 4 * s);
        for (int k = 0; k < m; k++) {
            // prefetch next edge's gather (clamped for exhausted groups)
            float4 hn0, hn1;
            if (k + 1 < m) {
                int kn = (k + 1 < deg) ? k + 1 : clampv;
                int cn = g_scol[start + kn];
                hn0 = *(const float4*)(g_h + (size_t)cn * 64 + 4 * s);
                hn1 = *(const float4*)(g_h + (size_t)cn * 64 + 32 + 4 * s);
            }
            float d0 = hr0.x * hc0.x + hr0.y * hc0.y + hr0.z * hc0.z + hr0.w * hc0.w;
            float d1 = hr1.x * hc1.x + hr1.y * hc1.y + hr1.z * hc1.z + hr1.w * hc1.w;
            d0 += __shfl_xor_sync(0xffffffffu, d0, 4);
            d1 += __shfl_xor_sync(0xffffffffu, d1, 4);
            d0 += __shfl_xor_sync(0xffffffffu, d0, 2);
            d1 += __shfl_xor_sync(0xffffffffu, d1, 2);
            d0 += __shfl_xor_sync(0xffffffffu, d0, 1);
            d1 += __shfl_xor_sync(0xffffffffu, d1, 1);
            bool valid = (k < deg);
            float ex0 = valid ? __expf(leaky(d0)) : 0.f;
            float ex1 = valid ? __expf(leaky(d1)) : 0.f;
            se0 += ex0;
            se1 += ex1;
            a0.x += ex0 * hc0.x; a0.y += ex0 * hc0.y;
            a0.z += ex0 * hc0.z; a0.w += ex0 * hc0.w;
            a1.x += ex1 * hc1.x; a1.y += ex1 * hc1.y;
            a1.z += ex1 * hc1.z; a1.w += ex1 * hc1.w;
            hc0 = hn0; hc1 = hn1;
        }
    }

    // every lane of the group holds the full dot-reduced weights -> direct write
    float sc0 = 1.0f / (se0 + EPS_F);
    float sc1 = 1.0f / (se1 + EPS_F);
    *(float4*)(out + (size_t)r * 64 + 4 * s) =
        make_float4(a0.x * sc0, a0.y * sc0, a0.z * sc0, a0.w * sc0);
    *(float4*)(out + (size_t)r * 64 + 32 + 4 * s) =
        make_float4(a1.x * sc1, a1.y * sc1, a1.z * sc1, a1.w * sc1);
}

// ---------------- launcher ---------------------------------------------------
// Two-stream fork: project_kernel runs concurrently with the
// zero->hist->scan->permute chain; both join before row_kernel.
static cudaStream_t g_s2 = nullptr;
static cudaEvent_t  g_ev_fork = nullptr;
static cudaEvent_t  g_ev_join = nullptr;

extern "C" void kernel_launch(void* const* d_in, const int* in_sizes, int n_in,
                              void* d_out, int out_size) {
    const float* ego = (const float*)d_in[0];   // [1M, 64] f32
    const float* W   = (const float*)d_in[1];   // [2, 64, 32] f32
    const float* b   = (const float*)d_in[2];   // [2, 1, 32] f32
    const int* row   = (const int*)d_in[3];     // [8M] i32 (destination)
    const int* col   = (const int*)d_in[4];     // [8M] i32 (source)
    float* out       = (float*)d_out;           // [1M, 64] f32

    if (g_s2 == nullptr) {
        cudaStreamCreateWithFlags(&g_s2, cudaStreamNonBlocking);
        cudaEventCreateWithFlags(&g_ev_fork, cudaEventDisableTiming);
        cudaEventCreateWithFlags(&g_ev_join, cudaEventDisableTiming);
    }

    // fork: side stream runs the projection concurrently
    cudaEventRecord(g_ev_fork, 0);
    cudaStreamWaitEvent(g_s2, g_ev_fork, 0);
    project_kernel<<<2048, 256, 0, g_s2>>>(ego, W, b);
    cudaEventRecord(g_ev_join, g_s2);

    // main stream: build sorted-edge structure
    zero_kernel<<<1024, 256>>>();
    hist_kernel<<<4096, 256>>>(row);
    scan1_kernel<<<SCAN_NB, 1024>>>();
    scan2_kernel<<<1, 1024>>>();
    scan3_kernel<<<SCAN_NB, 1024>>>();
    permute_kernel<<<4096, 256>>>(row, col);

    // join: row pass needs both g_h (projection) and g_scol/g_off (sort)
    cudaStreamWaitEvent(0, g_ev_join, 0);
    row_kernel<<<31250, 256>>>(out);            // 4 rows per warp, 8 warps/block
}